// round 6
// baseline (speedup 1.0000x reference)
#include <cuda_runtime.h>

#define B   64
#define P   196
#define ENC 2048
#define H   1024
#define AA  1024
#define EE  512
#define VV  10000
#define TC  32
#define T   31
#define MT  (T * B)          // 1984 live rows of h-history / emb-gates

// ---- output layout: concat(predictions, alphas, caps, dec_lens, ind), float32
#define OFF_PRED  0ULL
#define OFF_ALPHA 19840000ULL
#define OFF_CAPS  20228864ULL
#define OFF_DLEN  20230912ULL
#define OFF_IND   20230976ULL

// ---- device scratch
__device__ int   g_ind[B];
__device__ int   g_dlen[B];
__device__ int   g_caps[B * TC];
__device__ float g_mean[B * ENC];
__device__ float g_h[B * H];
__device__ float g_c[B * H];
__device__ float g_encatt[(size_t)B * P * AA];    // 51.4 MB
__device__ float g_part1[2 * B * 7168];           // split-K=2 partials of h @ [Wdec;Wbeta;Whh]^T
__device__ float g_alog[B * P];
__device__ float g_awe[B * ENC];
__device__ float g_part2[4 * B * 4096];           // split-K=4 partials of awe @ W_ih[:,512:]^T
__device__ float g_initp[8 * B * 2048];           // split-K=8 partials of init GEMM
__device__ float g_embg[(size_t)2048 * 4096];     // emb @ W_ih[:,:512]^T (padded to 2048 rows)
__device__ float g_hhist[(size_t)2048 * H];       // h_new history (padded to 2048 rows)

__device__ __forceinline__ float sigf(float x) { return 1.f / (1.f + expf(-x)); }

enum { AM_PLAIN = 0, AM_ENC = 1, AM_EMB = 2 };
enum { BM_PLAIN = 0, BM_G1 = 1, BM_G2 = 2 };
enum { OM_PART = 0, OM_PLAIN = 1, OM_PRED = 2 };

// ============================================================
// stable argsort of -lengths; emit ind/dec_lens/caps tail of output
// ============================================================
__global__ void k_sort(const int* __restrict__ lengths,
                       const int* __restrict__ caps_in,
                       float* __restrict__ out) {
    int i = threadIdx.x;
    int li = lengths[i];
    int r = 0;
    for (int j = 0; j < B; j++) {
        int lj = lengths[j];
        if (lj > li || (lj == li && j < i)) r++;
    }
    g_ind[r]  = i;
    g_dlen[r] = li - 1;
    out[OFF_DLEN + r] = (float)(li - 1);
    out[OFF_IND + r]  = (float)i;
    for (int t = 0; t < TC; t++) {
        int cv = caps_in[i * TC + t];
        g_caps[r * TC + t] = cv;
        out[OFF_CAPS + (size_t)r * TC + t] = (float)cv;
    }
}

// ============================================================
// mean over P of sorted enc_out
// ============================================================
__global__ __launch_bounds__(256) void k_mean(const float* __restrict__ enc_out) {
    int b = blockIdx.x >> 3, ch = blockIdx.x & 7;
    int e = ch * 256 + threadIdx.x;
    const float* src = enc_out + (size_t)g_ind[b] * P * ENC + e;
    float s = 0.f;
    #pragma unroll 4
    for (int p = 0; p < P; p++) s += src[(size_t)p * ENC];
    g_mean[(size_t)b * ENC + e] = s * (1.f / 196.f);
}

// ============================================================
// BIG GEMM: 128x128 tile, KT=16, 256 threads, 8x8 microtile (split 4+4)
// C[M,N] = A[M,K] @ W[N,K]^T (+bias)
// ============================================================
template <int AMODE, int OMODE>
__global__ __launch_bounds__(256, 2) void gemmBig(
    const float* __restrict__ A, int lda,
    const float* __restrict__ W, int ldw,
    const float* __restrict__ bias,
    float* __restrict__ C, int N, int K)
{
    __shared__ float As[16][132];
    __shared__ float Bs[16][132];
    __shared__ int   srow[128];

    const int tid = threadIdx.x;
    const int tx = tid & 15, ty = tid >> 4;
    const int nbase = blockIdx.x * 128;
    const int mbase = blockIdx.y * 128;
    const int lr = tid >> 2;          // 0..63
    const int lq = (tid & 3) * 4;     // 0,4,8,12

    if (AMODE != AM_PLAIN) {
        if (tid < 128) {
            int m = mbase + tid;
            srow[tid] = (AMODE == AM_ENC) ? (g_ind[m / 196] * 196 + (m % 196))
                                          : g_caps[(m & 63) * TC + (m >> 6)];
        }
        __syncthreads();
    }

    const float* pA0;
    const float* pA1;
    if (AMODE == AM_PLAIN) {
        pA0 = A + (size_t)(mbase + lr) * lda + lq;
        pA1 = A + (size_t)(mbase + lr + 64) * lda + lq;
    } else {
        pA0 = A + (size_t)srow[lr] * lda + lq;
        pA1 = A + (size_t)srow[lr + 64] * lda + lq;
    }
    int n0 = nbase + lr;       if (n0 >= N) n0 = N - 1;   // clamp: store is guarded
    int n1 = nbase + lr + 64;  if (n1 >= N) n1 = N - 1;
    const float* pB0 = W + (size_t)n0 * ldw + lq;
    const float* pB1 = W + (size_t)n1 * ldw + lq;

    float4 a0 = *(const float4*)pA0, a1 = *(const float4*)pA1;
    float4 b0 = *(const float4*)pB0, b1 = *(const float4*)pB1;

    float acc[8][8];
    #pragma unroll
    for (int i = 0; i < 8; i++)
        #pragma unroll
        for (int j = 0; j < 8; j++) acc[i][j] = 0.f;

    const int nT = K >> 4;
    for (int it = 0; it < nT; it++) {
        __syncthreads();
        As[lq + 0][lr] = a0.x; As[lq + 1][lr] = a0.y; As[lq + 2][lr] = a0.z; As[lq + 3][lr] = a0.w;
        As[lq + 0][lr + 64] = a1.x; As[lq + 1][lr + 64] = a1.y; As[lq + 2][lr + 64] = a1.z; As[lq + 3][lr + 64] = a1.w;
        Bs[lq + 0][lr] = b0.x; Bs[lq + 1][lr] = b0.y; Bs[lq + 2][lr] = b0.z; Bs[lq + 3][lr] = b0.w;
        Bs[lq + 0][lr + 64] = b1.x; Bs[lq + 1][lr + 64] = b1.y; Bs[lq + 2][lr + 64] = b1.z; Bs[lq + 3][lr + 64] = b1.w;
        __syncthreads();
        if (it + 1 < nT) {
            pA0 += 16; pA1 += 16; pB0 += 16; pB1 += 16;
            a0 = *(const float4*)pA0; a1 = *(const float4*)pA1;
            b0 = *(const float4*)pB0; b1 = *(const float4*)pB1;
        }
        #pragma unroll
        for (int kk = 0; kk < 16; kk++) {
            float4 x0 = *(const float4*)&As[kk][ty * 4];
            float4 x1 = *(const float4*)&As[kk][64 + ty * 4];
            float4 y0 = *(const float4*)&Bs[kk][tx * 4];
            float4 y1 = *(const float4*)&Bs[kk][64 + tx * 4];
            float xv[8] = {x0.x, x0.y, x0.z, x0.w, x1.x, x1.y, x1.z, x1.w};
            float yv[8] = {y0.x, y0.y, y0.z, y0.w, y1.x, y1.y, y1.z, y1.w};
            #pragma unroll
            for (int i = 0; i < 8; i++)
                #pragma unroll
                for (int j = 0; j < 8; j++) acc[i][j] += xv[i] * yv[j];
        }
    }

    #pragma unroll
    for (int i = 0; i < 8; i++) {
        int m = mbase + ((i < 4) ? (ty * 4 + i) : (64 + ty * 4 + i - 4));
        if (OMODE == OM_PRED) {
            if (m >= MT) continue;
            int tt = m >> 6, b = m & 63;
            float mf = (tt < g_dlen[b]) ? 1.f : 0.f;
            size_t oo = OFF_PRED + ((size_t)b * T + tt) * VV;
            #pragma unroll
            for (int j = 0; j < 8; j++) {
                int n = nbase + ((j < 4) ? (tx * 4 + j) : (64 + tx * 4 + j - 4));
                if (n < N) C[oo + n] = (acc[i][j] + bias[n]) * mf;
            }
        } else {
            #pragma unroll
            for (int j = 0; j < 8; j++) {
                int n = nbase + ((j < 4) ? (tx * 4 + j) : (64 + tx * 4 + j - 4));
                if (n < N) {
                    float v = acc[i][j];
                    if (OMODE == OM_PLAIN) v += bias[n];
                    C[(size_t)m * N + n] = v;
                }
            }
        }
    }
}

// ============================================================
// SMALL GEMM: 64x128 tile, KT=32, 256 threads, 4x8 microtile, split-K
// writes partials: C[(z*64+m)*N + n] (no bias)
// ============================================================
template <int BMODE>
__global__ __launch_bounds__(256, 3) void gemmSmall(
    const float* __restrict__ A, int lda,
    const float* __restrict__ W0, const float* __restrict__ W1, const float* __restrict__ W2,
    int ldw, int wofs,
    float* __restrict__ C, int N, int K)
{
    __shared__ float As[32][68];
    __shared__ float Bs[32][132];

    const int tid = threadIdx.x;
    const int tx = tid & 15, ty = tid >> 4;
    const int nbase = blockIdx.x * 128;
    const int kLen = K / gridDim.z;
    const int kStart = blockIdx.z * kLen;
    const int lr = tid >> 3;        // 0..31
    const int kq = (tid & 7) * 4;   // 0..28

    const float* pA0 = A + (size_t)lr * lda + kStart + kq;
    const float* pA1 = A + (size_t)(lr + 32) * lda + kStart + kq;

    const float* pB[4];
    #pragma unroll
    for (int q = 0; q < 4; q++) {
        int n = nbase + lr + q * 32;
        const float* w;
        if (BMODE == BM_PLAIN) {
            w = W0 + (size_t)n * ldw + wofs;
        } else if (BMODE == BM_G1) {   // [0,1024)=W0, [1024,3072)=W1, [3072,7168)=W2, K=1024
            if (n < 1024)      w = W0 + (size_t)n * 1024;
            else if (n < 3072) w = W1 + (size_t)(n - 1024) * 1024;
            else               w = W2 + (size_t)(n - 3072) * 1024;
        } else {                        // BM_G2: [0,1024)=W0, [1024,2048)=W1, K=2048
            w = (n < 1024) ? (W0 + (size_t)n * 2048) : (W1 + (size_t)(n - 1024) * 2048);
        }
        pB[q] = w + kStart + kq;
    }

    float4 a0 = *(const float4*)pA0, a1 = *(const float4*)pA1;
    float4 bb0 = *(const float4*)pB[0], bb1 = *(const float4*)pB[1];
    float4 bb2 = *(const float4*)pB[2], bb3 = *(const float4*)pB[3];

    float acc[4][8];
    #pragma unroll
    for (int i = 0; i < 4; i++)
        #pragma unroll
        for (int j = 0; j < 8; j++) acc[i][j] = 0.f;

    const int nT = kLen >> 5;
    for (int it = 0; it < nT; it++) {
        __syncthreads();
        As[kq + 0][lr] = a0.x; As[kq + 1][lr] = a0.y; As[kq + 2][lr] = a0.z; As[kq + 3][lr] = a0.w;
        As[kq + 0][lr + 32] = a1.x; As[kq + 1][lr + 32] = a1.y; As[kq + 2][lr + 32] = a1.z; As[kq + 3][lr + 32] = a1.w;
        Bs[kq + 0][lr]      = bb0.x; Bs[kq + 1][lr]      = bb0.y; Bs[kq + 2][lr]      = bb0.z; Bs[kq + 3][lr]      = bb0.w;
        Bs[kq + 0][lr + 32] = bb1.x; Bs[kq + 1][lr + 32] = bb1.y; Bs[kq + 2][lr + 32] = bb1.z; Bs[kq + 3][lr + 32] = bb1.w;
        Bs[kq + 0][lr + 64] = bb2.x; Bs[kq + 1][lr + 64] = bb2.y; Bs[kq + 2][lr + 64] = bb2.z; Bs[kq + 3][lr + 64] = bb2.w;
        Bs[kq + 0][lr + 96] = bb3.x; Bs[kq + 1][lr + 96] = bb3.y; Bs[kq + 2][lr + 96] = bb3.z; Bs[kq + 3][lr + 96] = bb3.w;
        __syncthreads();
        if (it + 1 < nT) {
            pA0 += 32; pA1 += 32;
            a0 = *(const float4*)pA0; a1 = *(const float4*)pA1;
            pB[0] += 32; pB[1] += 32; pB[2] += 32; pB[3] += 32;
            bb0 = *(const float4*)pB[0]; bb1 = *(const float4*)pB[1];
            bb2 = *(const float4*)pB[2]; bb3 = *(const float4*)pB[3];
        }
        #pragma unroll
        for (int kk = 0; kk < 32; kk++) {
            float4 x  = *(const float4*)&As[kk][ty * 4];
            float4 y0 = *(const float4*)&Bs[kk][tx * 4];
            float4 y1 = *(const float4*)&Bs[kk][64 + tx * 4];
            float xv[4] = {x.x, x.y, x.z, x.w};
            float yv[8] = {y0.x, y0.y, y0.z, y0.w, y1.x, y1.y, y1.z, y1.w};
            #pragma unroll
            for (int i = 0; i < 4; i++)
                #pragma unroll
                for (int j = 0; j < 8; j++) acc[i][j] += xv[i] * yv[j];
        }
    }

    #pragma unroll
    for (int i = 0; i < 4; i++) {
        int m = ty * 4 + i;
        size_t rowo = ((size_t)blockIdx.z * 64 + m) * N;
        #pragma unroll
        for (int j = 0; j < 8; j++) {
            int n = nbase + ((j < 4) ? (tx * 4 + j) : (64 + tx * 4 + j - 4));
            C[rowo + n] = acc[i][j];
        }
    }
}

// ============================================================
// combine init partials -> h0, c0 (+bias)
// ============================================================
__global__ void k_init(const float* __restrict__ bh, const float* __restrict__ bc) {
    int idx = blockIdx.x * 256 + threadIdx.x;   // < 64*2048
    int b = idx >> 11, n = idx & 2047;
    float s = 0.f;
    #pragma unroll
    for (int z = 0; z < 8; z++) s += g_initp[((size_t)z * B + b) * 2048 + n];
    if (n < 1024) g_h[b * H + n] = s + bh[n];
    else          g_c[b * H + (n - 1024)] = s + bc[n - 1024];
}

// ============================================================
// attention logits: a[b,p] = relu(enc_att[b,p,:] + dec[b,:]) . W_full
// (b_full dropped: softmax shift-invariant). one warp per (b,p)
// ============================================================
__global__ __launch_bounds__(256) void k_att(const float* __restrict__ bdec,
                                             const float* __restrict__ wfull) {
    int gw = blockIdx.x * 8 + (threadIdx.x >> 5);   // (b*196+p) < 12544
    int lane = threadIdx.x & 31;
    int b = gw / P;
    const float* ea = g_encatt + (size_t)gw * AA;
    const float* d0 = g_part1 + (size_t)b * 7168;
    const float* d1 = g_part1 + (size_t)(B + b) * 7168;
    float s = 0.f;
    #pragma unroll 8
    for (int a = lane; a < AA; a += 32) {
        float v = ea[a] + d0[a] + d1[a] + bdec[a];
        v = fmaxf(v, 0.f);
        s += v * wfull[a];
    }
    #pragma unroll
    for (int o = 16; o > 0; o >>= 1) s += __shfl_down_sync(0xffffffffu, s, o);
    if (lane == 0) g_alog[gw] = s;
}

// ============================================================
// fused softmax + context + gate
// ============================================================
__global__ __launch_bounds__(256) void k_ctx(const float* __restrict__ enc_out,
                                             const float* __restrict__ bbeta,
                                             int t, float* __restrict__ out) {
    __shared__ float al[P];
    __shared__ float red[256];
    int b = blockIdx.x >> 3, ch = blockIdx.x & 7;
    int tid = threadIdx.x;
    float v = (tid < P) ? g_alog[b * P + tid] : -3.0e38f;
    red[tid] = v;
    __syncthreads();
    for (int o = 128; o > 0; o >>= 1) { if (tid < o) red[tid] = fmaxf(red[tid], red[tid + o]); __syncthreads(); }
    float mx = red[0];
    __syncthreads();
    float e0 = (tid < P) ? expf(v - mx) : 0.f;
    red[tid] = e0;
    __syncthreads();
    for (int o = 128; o > 0; o >>= 1) { if (tid < o) red[tid] += red[tid + o]; __syncthreads(); }
    float inv = 1.f / red[0];
    if (tid < P) {
        float a = e0 * inv;
        al[tid] = a;
        if (ch == 0) {
            float mf = (t < g_dlen[b]) ? 1.f : 0.f;
            out[OFF_ALPHA + ((size_t)b * T + t) * P + tid] = a * mf;
        }
    }
    __syncthreads();
    int e = ch * 256 + tid;
    const float* src = enc_out + (size_t)g_ind[b] * P * ENC + e;
    float s = 0.f;
    #pragma unroll 4
    for (int p = 0; p < P; p++) s += src[(size_t)p * ENC] * al[p];
    float beta = g_part1[(size_t)b * 7168 + 1024 + e]
               + g_part1[(size_t)(B + b) * 7168 + 1024 + e] + bbeta[e];
    g_awe[(size_t)b * ENC + e] = s * sigf(beta);
}

// ============================================================
// LSTM pointwise: embg + 4 ih partials + 2 hh partials + biases -> h,c
// ============================================================
__global__ void k_lstm(const float* __restrict__ bih, const float* __restrict__ bhh, int t) {
    int idx = blockIdx.x * 256 + threadIdx.x;   // < 65536
    int b = idx >> 10, j = idx & 1023;
    const float* pe = g_embg + ((size_t)t * B + b) * 4096;
    const float* h0 = g_part1 + (size_t)b * 7168 + 3072;
    const float* h1 = g_part1 + (size_t)(B + b) * 7168 + 3072;
    float g4[4];
    #pragma unroll
    for (int q = 0; q < 4; q++) {
        int jj = j + q * 1024;
        float s = pe[jj] + bih[jj] + h0[jj] + h1[jj] + bhh[jj];
        #pragma unroll
        for (int z = 0; z < 4; z++) s += g_part2[((size_t)z * B + b) * 4096 + jj];
        g4[q] = s;
    }
    float c = g_c[idx];
    float cn = sigf(g4[1]) * c + sigf(g4[0]) * tanhf(g4[2]);
    float hn = sigf(g4[3]) * tanhf(cn);
    g_hhist[((size_t)t * B + b) * H + j] = hn;
    if (t < g_dlen[b]) { g_c[idx] = cn; g_h[idx] = hn; }
}

// ============================================================
extern "C" void kernel_launch(void* const* d_in, const int* in_sizes, int n_in,
                              void* d_out, int out_size) {
    const float* enc_out   = (const float*)d_in[0];
    const int*   caps      = (const int*)  d_in[1];
    const int*   lengths   = (const int*)  d_in[2];
    const float* W_enc_att = (const float*)d_in[3];
    const float* b_enc_att = (const float*)d_in[4];
    const float* W_dec_att = (const float*)d_in[5];
    const float* b_dec_att = (const float*)d_in[6];
    const float* W_full    = (const float*)d_in[7];
    // d_in[8] = b_full (unused: softmax shift-invariant)
    const float* emb       = (const float*)d_in[9];
    const float* W_ih      = (const float*)d_in[10];
    const float* b_ih      = (const float*)d_in[11];
    const float* W_hh      = (const float*)d_in[12];
    const float* b_hh      = (const float*)d_in[13];
    const float* W_init_h  = (const float*)d_in[14];
    const float* b_init_h  = (const float*)d_in[15];
    const float* W_init_c  = (const float*)d_in[16];
    const float* b_init_c  = (const float*)d_in[17];
    const float* W_beta    = (const float*)d_in[18];
    const float* b_beta    = (const float*)d_in[19];
    const float* W_fc      = (const float*)d_in[20];
    const float* b_fc      = (const float*)d_in[21];
    float* out = (float*)d_out;

    float *p_mean, *p_h, *p_encatt, *p_part1, *p_awe, *p_part2, *p_initp, *p_embg, *p_hhist;
    cudaGetSymbolAddress((void**)&p_mean,   g_mean);
    cudaGetSymbolAddress((void**)&p_h,      g_h);
    cudaGetSymbolAddress((void**)&p_encatt, g_encatt);
    cudaGetSymbolAddress((void**)&p_part1,  g_part1);
    cudaGetSymbolAddress((void**)&p_awe,    g_awe);
    cudaGetSymbolAddress((void**)&p_part2,  g_part2);
    cudaGetSymbolAddress((void**)&p_initp,  g_initp);
    cudaGetSymbolAddress((void**)&p_embg,   g_embg);
    cudaGetSymbolAddress((void**)&p_hhist,  g_hhist);

    // ---- setup
    k_sort<<<1, 64>>>(lengths, caps, out);
    k_mean<<<512, 256>>>(enc_out);
    // fused [h0|c0] partials: mean @ [W_init_h;W_init_c]^T  (N=2048, K=2048, split-K=8)
    gemmSmall<BM_G2><<<dim3(16, 1, 8), 256>>>(
        p_mean, ENC, W_init_h, W_init_c, nullptr, 0, 0, p_initp, 2048, 2048);
    k_init<<<512, 256>>>(b_init_h, b_init_c);
    // enc_att = eo_sorted @ W_enc_att^T + b   (12544 x 1024, K=2048)
    gemmBig<AM_ENC, OM_PLAIN><<<dim3(8, 98), 256>>>(
        enc_out, ENC, W_enc_att, ENC, b_enc_att, p_encatt, AA, ENC);
    // emb-part of LSTM gates: (1984[pad 2048] x 4096, K=512)
    gemmBig<AM_EMB, OM_PART><<<dim3(32, 16), 256>>>(
        emb, EE, W_ih, 2560, nullptr, p_embg, 4096, EE);

    // ---- 31 sequential decode steps
    for (int t = 0; t < T; t++) {
        // fused [dec | beta | hh] = h @ [Wdec;Wbeta;Whh]^T  (N=7168, K=1024, split-K=2)
        gemmSmall<BM_G1><<<dim3(56, 1, 2), 256>>>(
            p_h, H, W_dec_att, W_beta, W_hh, 0, 0, p_part1, 7168, 1024);
        k_att<<<1568, 256>>>(b_dec_att, W_full);
        k_ctx<<<512, 256>>>(enc_out, b_beta, t, out);
        // awe-part of gates: awe @ W_ih[:,512:]^T  (N=4096, K=2048, split-K=4)
        gemmSmall<BM_PLAIN><<<dim3(32, 1, 4), 256>>>(
            p_awe, ENC, W_ih, nullptr, nullptr, 2560, 512, p_part2, 4096, 2048);
        k_lstm<<<256, 256>>>(b_ih, b_hh, t);
    }

    // ---- batched predictions: h_hist @ W_fc^T + b_fc, masked (1984 x 10000, K=1024)
    gemmBig<AM_PLAIN, OM_PRED><<<dim3(79, 16), 256>>>(
        p_hhist, H, W_fc, H, b_fc, out, VV, H);

    (void)in_sizes; (void)n_in; (void)out_size;
}

// round 7
// speedup vs baseline: 1.0979x; 1.0979x over previous
#include <cuda_runtime.h>

#define B   64
#define P   196
#define ENC 2048
#define H   1024
#define AA  1024
#define EE  512
#define VV  10000
#define TC  32
#define T   31
#define MT  (T * B)          // 1984 live rows of h-history / emb-gates

// ---- output layout: concat(predictions, alphas, caps, dec_lens, ind), float32
#define OFF_PRED  0ULL
#define OFF_ALPHA 19840000ULL
#define OFF_CAPS  20228864ULL
#define OFF_DLEN  20230912ULL
#define OFF_IND   20230976ULL

// ---- device scratch
__device__ int   g_ind[B];
__device__ int   g_dlen[B];
__device__ int   g_caps[B * TC];
__device__ float g_mean[B * ENC];
__device__ float g_h[B * H];
__device__ float g_c[B * H];
__device__ float g_encatt[(size_t)B * P * AA];    // 51.4 MB
__device__ float g_part1[2 * B * 7168];           // split-K=2 partials of h @ [Wdec;Wbeta;Whh]^T
__device__ float g_alog[B * P];
__device__ float g_awe[B * ENC];
__device__ float g_part2[4 * B * 4096];           // split-K=4 partials of awe @ W_ih[:,512:]^T
__device__ float g_initp[8 * B * 2048];           // split-K=8 partials of init GEMM
__device__ float g_embg[(size_t)2048 * 4096];     // emb @ W_ih[:,:512]^T (padded rows)
__device__ float g_hhist[(size_t)2048 * H];       // h_new history (padded rows)

__device__ __forceinline__ float sigf(float x) { return 1.f / (1.f + expf(-x)); }

typedef unsigned long long u64;
__device__ __forceinline__ u64 splat2(float x) {
    u64 r; asm("mov.b64 %0, {%1, %1};" : "=l"(r) : "f"(x)); return r;
}
__device__ __forceinline__ void ffma2(u64& c, u64 a, u64 b) {
    asm("fma.rn.f32x2 %0, %1, %2, %0;" : "+l"(c) : "l"(a), "l"(b));
}
__device__ __forceinline__ float2 unpk(u64 v) {
    float2 f; asm("mov.b64 {%0, %1}, %2;" : "=f"(f.x), "=f"(f.y) : "l"(v)); return f;
}

enum { AM_PLAIN = 0, AM_ENC = 1, AM_EMB = 2 };
enum { BM_PLAIN = 0, BM_G1 = 1, BM_G2 = 2 };
enum { OM_PART = 0, OM_PLAIN = 1, OM_PRED = 2 };

// ============================================================
// stable argsort of -lengths; emit ind/dec_lens/caps tail of output
// ============================================================
__global__ void k_sort(const int* __restrict__ lengths,
                       const int* __restrict__ caps_in,
                       float* __restrict__ out) {
    int i = threadIdx.x;
    int li = lengths[i];
    int r = 0;
    for (int j = 0; j < B; j++) {
        int lj = lengths[j];
        if (lj > li || (lj == li && j < i)) r++;
    }
    g_ind[r]  = i;
    g_dlen[r] = li - 1;
    out[OFF_DLEN + r] = (float)(li - 1);
    out[OFF_IND + r]  = (float)i;
    for (int t = 0; t < TC; t++) {
        int cv = caps_in[i * TC + t];
        g_caps[r * TC + t] = cv;
        out[OFF_CAPS + (size_t)r * TC + t] = (float)cv;
    }
}

// ============================================================
// mean over P of sorted enc_out
// ============================================================
__global__ __launch_bounds__(256) void k_mean(const float* __restrict__ enc_out) {
    int b = blockIdx.x >> 3, ch = blockIdx.x & 7;
    int e = ch * 256 + threadIdx.x;
    const float* src = enc_out + (size_t)g_ind[b] * P * ENC + e;
    float s = 0.f;
    #pragma unroll 4
    for (int p = 0; p < P; p++) s += src[(size_t)p * ENC];
    g_mean[(size_t)b * ENC + e] = s * (1.f / 196.f);
}

// ============================================================
// BIG GEMM: 128x128 tile, KT=16, 256 threads, 8x8 microtile, f32x2 FMA
// C[M,N] = A[M,K] @ W[N,K]^T (+bias)
// ============================================================
template <int AMODE, int OMODE>
__global__ __launch_bounds__(256, 2) void gemmBig(
    const float* __restrict__ A, int lda,
    const float* __restrict__ W, int ldw,
    const float* __restrict__ bias,
    float* __restrict__ C, int N, int K)
{
    __shared__ float As[16][132];
    __shared__ float Bs[16][132];
    __shared__ int   srow[128];

    const int tid = threadIdx.x;
    const int tx = tid & 15, ty = tid >> 4;
    const int nbase = blockIdx.x * 128;
    const int mbase = blockIdx.y * 128;
    const int lr = tid >> 2;          // 0..63
    const int lq = (tid & 3) * 4;     // 0,4,8,12

    if (AMODE != AM_PLAIN) {
        if (tid < 128) {
            int m = mbase + tid;
            srow[tid] = (AMODE == AM_ENC) ? (g_ind[m / 196] * 196 + (m % 196))
                                          : g_caps[(m & 63) * TC + (m >> 6)];
        }
        __syncthreads();
    }

    const float* pA0;
    const float* pA1;
    if (AMODE == AM_PLAIN) {
        pA0 = A + (size_t)(mbase + lr) * lda + lq;
        pA1 = A + (size_t)(mbase + lr + 64) * lda + lq;
    } else {
        pA0 = A + (size_t)srow[lr] * lda + lq;
        pA1 = A + (size_t)srow[lr + 64] * lda + lq;
    }
    int n0 = nbase + lr;       if (n0 >= N) n0 = N - 1;   // clamp: store is guarded
    int n1 = nbase + lr + 64;  if (n1 >= N) n1 = N - 1;
    const float* pB0 = W + (size_t)n0 * ldw + lq;
    const float* pB1 = W + (size_t)n1 * ldw + lq;

    float4 a0 = *(const float4*)pA0, a1 = *(const float4*)pA1;
    float4 b0 = *(const float4*)pB0, b1 = *(const float4*)pB1;

    u64 acc[8][4];
    #pragma unroll
    for (int i = 0; i < 8; i++)
        #pragma unroll
        for (int j = 0; j < 4; j++) acc[i][j] = 0ULL;

    const int nT = K >> 4;
    for (int it = 0; it < nT; it++) {
        __syncthreads();
        As[lq + 0][lr] = a0.x; As[lq + 1][lr] = a0.y; As[lq + 2][lr] = a0.z; As[lq + 3][lr] = a0.w;
        As[lq + 0][lr + 64] = a1.x; As[lq + 1][lr + 64] = a1.y; As[lq + 2][lr + 64] = a1.z; As[lq + 3][lr + 64] = a1.w;
        Bs[lq + 0][lr] = b0.x; Bs[lq + 1][lr] = b0.y; Bs[lq + 2][lr] = b0.z; Bs[lq + 3][lr] = b0.w;
        Bs[lq + 0][lr + 64] = b1.x; Bs[lq + 1][lr + 64] = b1.y; Bs[lq + 2][lr + 64] = b1.z; Bs[lq + 3][lr + 64] = b1.w;
        __syncthreads();
        if (it + 1 < nT) {
            pA0 += 16; pA1 += 16; pB0 += 16; pB1 += 16;
            a0 = *(const float4*)pA0; a1 = *(const float4*)pA1;
            b0 = *(const float4*)pB0; b1 = *(const float4*)pB1;
        }
        #pragma unroll
        for (int kk = 0; kk < 16; kk++) {
            float4 x0 = *(const float4*)&As[kk][ty * 4];
            float4 x1 = *(const float4*)&As[kk][64 + ty * 4];
            double2 yq0 = *(const double2*)&Bs[kk][tx * 4];        // packed col pairs 0,1
            double2 yq1 = *(const double2*)&Bs[kk][64 + tx * 4];   // packed col pairs 2,3
            u64 y0 = __double_as_longlong(yq0.x);
            u64 y1 = __double_as_longlong(yq0.y);
            u64 y2 = __double_as_longlong(yq1.x);
            u64 y3 = __double_as_longlong(yq1.y);
            float xs[8] = {x0.x, x0.y, x0.z, x0.w, x1.x, x1.y, x1.z, x1.w};
            #pragma unroll
            for (int i = 0; i < 8; i++) {
                u64 xi = splat2(xs[i]);
                ffma2(acc[i][0], xi, y0);
                ffma2(acc[i][1], xi, y1);
                ffma2(acc[i][2], xi, y2);
                ffma2(acc[i][3], xi, y3);
            }
        }
    }

    #pragma unroll
    for (int i = 0; i < 8; i++) {
        int m = mbase + ((i < 4) ? (ty * 4 + i) : (64 + ty * 4 + i - 4));
        float av[8];
        #pragma unroll
        for (int jp = 0; jp < 4; jp++) {
            float2 f = unpk(acc[i][jp]);
            av[jp * 2] = f.x; av[jp * 2 + 1] = f.y;
        }
        if (OMODE == OM_PRED) {
            if (m >= MT) continue;
            int tt = m >> 6, b = m & 63;
            float mf = (tt < g_dlen[b]) ? 1.f : 0.f;
            size_t oo = OFF_PRED + ((size_t)b * T + tt) * VV;
            #pragma unroll
            for (int j = 0; j < 8; j++) {
                int n = nbase + ((j < 4) ? (tx * 4 + j) : (64 + tx * 4 + j - 4));
                if (n < N) C[oo + n] = (av[j] + bias[n]) * mf;
            }
        } else {
            #pragma unroll
            for (int j = 0; j < 8; j++) {
                int n = nbase + ((j < 4) ? (tx * 4 + j) : (64 + tx * 4 + j - 4));
                if (n < N) {
                    float v = av[j];
                    if (OMODE == OM_PLAIN) v += bias[n];
                    C[(size_t)m * N + n] = v;
                }
            }
        }
    }
}

// ============================================================
// SMALL GEMM: 64x128 tile, KT=32, 256 threads, 4x8 microtile, f32x2, split-K
// writes partials: C[(z*64+m)*N + n] (no bias)
// ============================================================
template <int BMODE>
__global__ __launch_bounds__(256, 3) void gemmSmall(
    const float* __restrict__ A, int lda,
    const float* __restrict__ W0, const float* __restrict__ W1, const float* __restrict__ W2,
    int ldw, int wofs,
    float* __restrict__ C, int N, int K)
{
    __shared__ float As[32][68];
    __shared__ float Bs[32][132];

    const int tid = threadIdx.x;
    const int tx = tid & 15, ty = tid >> 4;
    const int nbase = blockIdx.x * 128;
    const int kLen = K / gridDim.z;
    const int kStart = blockIdx.z * kLen;
    const int lr = tid >> 3;        // 0..31
    const int kq = (tid & 7) * 4;   // 0..28

    const float* pA0 = A + (size_t)lr * lda + kStart + kq;
    const float* pA1 = A + (size_t)(lr + 32) * lda + kStart + kq;

    const float* pB[4];
    #pragma unroll
    for (int q = 0; q < 4; q++) {
        int n = nbase + lr + q * 32;
        const float* w;
        if (BMODE == BM_PLAIN) {
            w = W0 + (size_t)n * ldw + wofs;
        } else if (BMODE == BM_G1) {   // [0,1024)=W0, [1024,3072)=W1, [3072,7168)=W2, K=1024
            if (n < 1024)      w = W0 + (size_t)n * 1024;
            else if (n < 3072) w = W1 + (size_t)(n - 1024) * 1024;
            else               w = W2 + (size_t)(n - 3072) * 1024;
        } else {                        // BM_G2: [0,1024)=W0, [1024,2048)=W1, K=2048
            w = (n < 1024) ? (W0 + (size_t)n * 2048) : (W1 + (size_t)(n - 1024) * 2048);
        }
        pB[q] = w + kStart + kq;
    }

    float4 a0 = *(const float4*)pA0, a1 = *(const float4*)pA1;
    float4 bb0 = *(const float4*)pB[0], bb1 = *(const float4*)pB[1];
    float4 bb2 = *(const float4*)pB[2], bb3 = *(const float4*)pB[3];

    u64 acc[4][4];
    #pragma unroll
    for (int i = 0; i < 4; i++)
        #pragma unroll
        for (int j = 0; j < 4; j++) acc[i][j] = 0ULL;

    const int nT = kLen >> 5;
    for (int it = 0; it < nT; it++) {
        __syncthreads();
        As[kq + 0][lr] = a0.x; As[kq + 1][lr] = a0.y; As[kq + 2][lr] = a0.z; As[kq + 3][lr] = a0.w;
        As[kq + 0][lr + 32] = a1.x; As[kq + 1][lr + 32] = a1.y; As[kq + 2][lr + 32] = a1.z; As[kq + 3][lr + 32] = a1.w;
        Bs[kq + 0][lr]      = bb0.x; Bs[kq + 1][lr]      = bb0.y; Bs[kq + 2][lr]      = bb0.z; Bs[kq + 3][lr]      = bb0.w;
        Bs[kq + 0][lr + 32] = bb1.x; Bs[kq + 1][lr + 32] = bb1.y; Bs[kq + 2][lr + 32] = bb1.z; Bs[kq + 3][lr + 32] = bb1.w;
        Bs[kq + 0][lr + 64] = bb2.x; Bs[kq + 1][lr + 64] = bb2.y; Bs[kq + 2][lr + 64] = bb2.z; Bs[kq + 3][lr + 64] = bb2.w;
        Bs[kq + 0][lr + 96] = bb3.x; Bs[kq + 1][lr + 96] = bb3.y; Bs[kq + 2][lr + 96] = bb3.z; Bs[kq + 3][lr + 96] = bb3.w;
        __syncthreads();
        if (it + 1 < nT) {
            pA0 += 32; pA1 += 32;
            a0 = *(const float4*)pA0; a1 = *(const float4*)pA1;
            pB[0] += 32; pB[1] += 32; pB[2] += 32; pB[3] += 32;
            bb0 = *(const float4*)pB[0]; bb1 = *(const float4*)pB[1];
            bb2 = *(const float4*)pB[2]; bb3 = *(const float4*)pB[3];
        }
        #pragma unroll
        for (int kk = 0; kk < 32; kk++) {
            float4 x  = *(const float4*)&As[kk][ty * 4];
            double2 yq0 = *(const double2*)&Bs[kk][tx * 4];
            double2 yq1 = *(const double2*)&Bs[kk][64 + tx * 4];
            u64 y0 = __double_as_longlong(yq0.x);
            u64 y1 = __double_as_longlong(yq0.y);
            u64 y2 = __double_as_longlong(yq1.x);
            u64 y3 = __double_as_longlong(yq1.y);
            float xs[4] = {x.x, x.y, x.z, x.w};
            #pragma unroll
            for (int i = 0; i < 4; i++) {
                u64 xi = splat2(xs[i]);
                ffma2(acc[i][0], xi, y0);
                ffma2(acc[i][1], xi, y1);
                ffma2(acc[i][2], xi, y2);
                ffma2(acc[i][3], xi, y3);
            }
        }
    }

    #pragma unroll
    for (int i = 0; i < 4; i++) {
        int m = ty * 4 + i;
        size_t rowo = ((size_t)blockIdx.z * 64 + m) * N;
        #pragma unroll
        for (int jp = 0; jp < 4; jp++) {
            float2 f = unpk(acc[i][jp]);
            int n = nbase + ((jp < 2) ? (tx * 4 + jp * 2) : (64 + tx * 4 + (jp - 2) * 2));
            C[rowo + n]     = f.x;
            C[rowo + n + 1] = f.y;
        }
    }
}

// ============================================================
// combine init partials -> h0, c0 (+bias)
// ============================================================
__global__ void k_init(const float* __restrict__ bh, const float* __restrict__ bc) {
    int idx = blockIdx.x * 256 + threadIdx.x;   // < 64*2048
    int b = idx >> 11, n = idx & 2047;
    float s = 0.f;
    #pragma unroll
    for (int z = 0; z < 8; z++) s += g_initp[((size_t)z * B + b) * 2048 + n];
    if (n < 1024) g_h[b * H + n] = s + bh[n];
    else          g_c[b * H + (n - 1024)] = s + bc[n - 1024];
}

// ============================================================
// attention logits: a[b,p] = relu(enc_att[b,p,:] + dec[b,:]) . W_full
// (b_full dropped: softmax shift-invariant). one warp per (b,p)
// ============================================================
__global__ __launch_bounds__(256) void k_att(const float* __restrict__ bdec,
                                             const float* __restrict__ wfull) {
    int gw = blockIdx.x * 8 + (threadIdx.x >> 5);   // (b*196+p) < 12544
    int lane = threadIdx.x & 31;
    int b = gw / P;
    const float* ea = g_encatt + (size_t)gw * AA;
    const float* d0 = g_part1 + (size_t)b * 7168;
    const float* d1 = g_part1 + (size_t)(B + b) * 7168;
    float s = 0.f;
    #pragma unroll 8
    for (int a = lane; a < AA; a += 32) {
        float v = ea[a] + d0[a] + d1[a] + bdec[a];
        v = fmaxf(v, 0.f);
        s += v * wfull[a];
    }
    #pragma unroll
    for (int o = 16; o > 0; o >>= 1) s += __shfl_down_sync(0xffffffffu, s, o);
    if (lane == 0) g_alog[gw] = s;
}

// ============================================================
// fused softmax + context + gate
// ============================================================
__global__ __launch_bounds__(256) void k_ctx(const float* __restrict__ enc_out,
                                             const float* __restrict__ bbeta,
                                             int t, float* __restrict__ out) {
    __shared__ float al[P];
    __shared__ float red[256];
    int b = blockIdx.x >> 3, ch = blockIdx.x & 7;
    int tid = threadIdx.x;
    float v = (tid < P) ? g_alog[b * P + tid] : -3.0e38f;
    red[tid] = v;
    __syncthreads();
    for (int o = 128; o > 0; o >>= 1) { if (tid < o) red[tid] = fmaxf(red[tid], red[tid + o]); __syncthreads(); }
    float mx = red[0];
    __syncthreads();
    float e0 = (tid < P) ? expf(v - mx) : 0.f;
    red[tid] = e0;
    __syncthreads();
    for (int o = 128; o > 0; o >>= 1) { if (tid < o) red[tid] += red[tid + o]; __syncthreads(); }
    float inv = 1.f / red[0];
    if (tid < P) {
        float a = e0 * inv;
        al[tid] = a;
        if (ch == 0) {
            float mf = (t < g_dlen[b]) ? 1.f : 0.f;
            out[OFF_ALPHA + ((size_t)b * T + t) * P + tid] = a * mf;
        }
    }
    __syncthreads();
    int e = ch * 256 + tid;
    const float* src = enc_out + (size_t)g_ind[b] * P * ENC + e;
    float s = 0.f;
    #pragma unroll 4
    for (int p = 0; p < P; p++) s += src[(size_t)p * ENC] * al[p];
    float beta = g_part1[(size_t)b * 7168 + 1024 + e]
               + g_part1[(size_t)(B + b) * 7168 + 1024 + e] + bbeta[e];
    g_awe[(size_t)b * ENC + e] = s * sigf(beta);
}

// ============================================================
// LSTM pointwise: embg + 4 ih partials + 2 hh partials + biases -> h,c
// ============================================================
__global__ void k_lstm(const float* __restrict__ bih, const float* __restrict__ bhh, int t) {
    int idx = blockIdx.x * 256 + threadIdx.x;   // < 65536
    int b = idx >> 10, j = idx & 1023;
    const float* pe = g_embg + ((size_t)t * B + b) * 4096;
    const float* h0 = g_part1 + (size_t)b * 7168 + 3072;
    const float* h1 = g_part1 + (size_t)(B + b) * 7168 + 3072;
    float g4[4];
    #pragma unroll
    for (int q = 0; q < 4; q++) {
        int jj = j + q * 1024;
        float s = pe[jj] + bih[jj] + h0[jj] + h1[jj] + bhh[jj];
        #pragma unroll
        for (int z = 0; z < 4; z++) s += g_part2[((size_t)z * B + b) * 4096 + jj];
        g4[q] = s;
    }
    float c = g_c[idx];
    float cn = sigf(g4[1]) * c + sigf(g4[0]) * tanhf(g4[2]);
    float hn = sigf(g4[3]) * tanhf(cn);
    g_hhist[((size_t)t * B + b) * H + j] = hn;
    if (t < g_dlen[b]) { g_c[idx] = cn; g_h[idx] = hn; }
}

// ============================================================
extern "C" void kernel_launch(void* const* d_in, const int* in_sizes, int n_in,
                              void* d_out, int out_size) {
    const float* enc_out   = (const float*)d_in[0];
    const int*   caps      = (const int*)  d_in[1];
    const int*   lengths   = (const int*)  d_in[2];
    const float* W_enc_att = (const float*)d_in[3];
    const float* b_enc_att = (const float*)d_in[4];
    const float* W_dec_att = (const float*)d_in[5];
    const float* b_dec_att = (const float*)d_in[6];
    const float* W_full    = (const float*)d_in[7];
    // d_in[8] = b_full (unused: softmax shift-invariant)
    const float* emb       = (const float*)d_in[9];
    const float* W_ih      = (const float*)d_in[10];
    const float* b_ih      = (const float*)d_in[11];
    const float* W_hh      = (const float*)d_in[12];
    const float* b_hh      = (const float*)d_in[13];
    const float* W_init_h  = (const float*)d_in[14];
    const float* b_init_h  = (const float*)d_in[15];
    const float* W_init_c  = (const float*)d_in[16];
    const float* b_init_c  = (const float*)d_in[17];
    const float* W_beta    = (const float*)d_in[18];
    const float* b_beta    = (const float*)d_in[19];
    const float* W_fc      = (const float*)d_in[20];
    const float* b_fc      = (const float*)d_in[21];
    float* out = (float*)d_out;

    float *p_mean, *p_h, *p_encatt, *p_part1, *p_awe, *p_part2, *p_initp, *p_embg, *p_hhist;
    cudaGetSymbolAddress((void**)&p_mean,   g_mean);
    cudaGetSymbolAddress((void**)&p_h,      g_h);
    cudaGetSymbolAddress((void**)&p_encatt, g_encatt);
    cudaGetSymbolAddress((void**)&p_part1,  g_part1);
    cudaGetSymbolAddress((void**)&p_awe,    g_awe);
    cudaGetSymbolAddress((void**)&p_part2,  g_part2);
    cudaGetSymbolAddress((void**)&p_initp,  g_initp);
    cudaGetSymbolAddress((void**)&p_embg,   g_embg);
    cudaGetSymbolAddress((void**)&p_hhist,  g_hhist);

    // ---- setup
    k_sort<<<1, 64>>>(lengths, caps, out);
    k_mean<<<512, 256>>>(enc_out);
    // fused [h0|c0] partials: mean @ [W_init_h;W_init_c]^T  (N=2048, K=2048, split-K=8)
    gemmSmall<BM_G2><<<dim3(16, 1, 8), 256>>>(
        p_mean, ENC, W_init_h, W_init_c, nullptr, 0, 0, p_initp, 2048, 2048);
    k_init<<<512, 256>>>(b_init_h, b_init_c);
    // enc_att = eo_sorted @ W_enc_att^T + b   (12544 x 1024, K=2048)
    gemmBig<AM_ENC, OM_PLAIN><<<dim3(8, 98), 256>>>(
        enc_out, ENC, W_enc_att, ENC, b_enc_att, p_encatt, AA, ENC);
    // emb-part of LSTM gates: (1984[pad 2048] x 4096, K=512)
    gemmBig<AM_EMB, OM_PART><<<dim3(32, 16), 256>>>(
        emb, EE, W_ih, 2560, nullptr, p_embg, 4096, EE);

    // ---- 31 sequential decode steps
    for (int t = 0; t < T; t++) {
        // fused [dec | beta | hh] = h @ [Wdec;Wbeta;Whh]^T  (N=7168, K=1024, split-K=2)
        gemmSmall<BM_G1><<<dim3(56, 1, 2), 256>>>(
            p_h, H, W_dec_att, W_beta, W_hh, 0, 0, p_part1, 7168, 1024);
        k_att<<<1568, 256>>>(b_dec_att, W_full);
        k_ctx<<<512, 256>>>(enc_out, b_beta, t, out);
        // awe-part of gates: awe @ W_ih[:,512:]^T  (N=4096, K=2048, split-K=4)
        gemmSmall<BM_PLAIN><<<dim3(32, 1, 4), 256>>>(
            p_awe, ENC, W_ih, nullptr, nullptr, 2560, 512, p_part2, 4096, 2048);
        k_lstm<<<256, 256>>>(b_ih, b_hh, t);
    }

    // ---- batched predictions: h_hist @ W_fc^T + b_fc, masked (1984 x 10000, K=1024)
    gemmBig<AM_PLAIN, OM_PRED><<<dim3(79, 16), 256>>>(
        p_hhist, H, W_fc, H, b_fc, out, VV, H);

    (void)in_sizes; (void)n_in; (void)out_size;
}